// round 1
// baseline (speedup 1.0000x reference)
#include <cuda_runtime.h>
#include <math.h>

// Problem constants (GaussianVoxelizer): grid 100x100x8, 128 gaussians, 16 features.
#define NVOX 80000
#define NG   128
#define NF   16
// Packed SoA fields per gaussian:
// 0..2  : mean x,y,z
// 3..5  : inv00, inv11, inv22
// 6..8  : 2*inv01, 2*inv02, 2*inv12
// 9     : opacity
// 10..25: opacity*feature[0..15]
// 26..28: bbox min x,y,z
// 29..31: bbox max x,y,z
#define FIELDS 32

__device__ float g_packed[FIELDS * NG];

__global__ void gv_prep_kernel(const float* __restrict__ means,
                               const float* __restrict__ opac,
                               const float* __restrict__ feats,
                               const float* __restrict__ covs) {
    int g = threadIdx.x;
    if (g >= NG) return;
    const float* C = covs + g * 9;
    float a = C[0], b = C[1], c = C[2];
    float d = C[4], e = C[5], f = C[8];
    // adjugate of symmetric 3x3
    float c00 = d * f - e * e;
    float c01 = c * e - b * f;
    float c02 = b * e - c * d;
    float det = a * c00 + b * c01 + c * c02;
    float id  = 1.0f / det;
    float i00 = c00 * id;
    float i01 = c01 * id;
    float i02 = c02 * id;
    float i11 = (a * f - c * c) * id;
    float i12 = (b * c - a * e) * id;
    float i22 = (a * d - b * b) * id;

    float mx = means[g * 3 + 0];
    float my = means[g * 3 + 1];
    float mz = means[g * 3 + 2];
    float op = opac[g];

    g_packed[0 * NG + g] = mx;
    g_packed[1 * NG + g] = my;
    g_packed[2 * NG + g] = mz;
    g_packed[3 * NG + g] = i00;
    g_packed[4 * NG + g] = i11;
    g_packed[5 * NG + g] = i22;
    g_packed[6 * NG + g] = 2.0f * i01;
    g_packed[7 * NG + g] = 2.0f * i02;
    g_packed[8 * NG + g] = 2.0f * i12;
    g_packed[9 * NG + g] = op;
#pragma unroll
    for (int k = 0; k < NF; k++)
        g_packed[(10 + k) * NG + g] = op * feats[g * NF + k];

    // Conservative AABB of {x : (x-mu)^T Cinv (x-mu) <= 4}: mu +- 2*sqrt(C_kk).
    const float margin = 1e-3f;
    float ex = 2.0f * sqrtf(fmaxf(a, 0.0f)) + margin;
    float ey = 2.0f * sqrtf(fmaxf(d, 0.0f)) + margin;
    float ez = 2.0f * sqrtf(fmaxf(f, 0.0f)) + margin;
    g_packed[26 * NG + g] = mx - ex;
    g_packed[27 * NG + g] = my - ey;
    g_packed[28 * NG + g] = mz - ez;
    g_packed[29 * NG + g] = mx + ex;
    g_packed[30 * NG + g] = my + ey;
    g_packed[31 * NG + g] = mz + ez;
}

__global__ __launch_bounds__(128) void gv_splat_kernel(const float* __restrict__ grid,
                                                       float* __restrict__ out) {
    __shared__ float sp[FIELDS * NG];   // 16 KB
    __shared__ int   s_list[NG];
    __shared__ int   s_cnt;

    int tid = threadIdx.x;

    // Cooperative load of gaussian SoA params into shared.
#pragma unroll
    for (int i = tid; i < FIELDS * NG; i += 128)
        sp[i] = g_packed[i];
    if (tid == 0) s_cnt = 0;
    __syncthreads();

    // Block voxel AABB (centers). n = (x*100 + y)*8 + z; coord = (i+0.5)*0.8 + lo.
    int n0 = blockIdx.x * 128;
    int n1 = n0 + 127;                      // 625*128 == 80000 exactly, no tail
    int x0 = n0 / 800, x1 = n1 / 800;
    float bxmin = (x0 + 0.5f) * 0.8f - 40.0f;
    float bxmax = (x1 + 0.5f) * 0.8f - 40.0f;
    float bymin, bymax;
    if (x0 == x1) {
        int y0 = (n0 % 800) / 8, y1 = (n1 % 800) / 8;
        bymin = (y0 + 0.5f) * 0.8f - 40.0f;
        bymax = (y1 + 0.5f) * 0.8f - 40.0f;
    } else {
        bymin = 0.5f * 0.8f - 40.0f;
        bymax = 99.5f * 0.8f - 40.0f;
    }
    float bzmin = 0.5f * 0.8f - 1.0f;
    float bzmax = 7.5f * 0.8f - 1.0f;

    // Cull: keep gaussian tid if its AABB overlaps the block AABB.
    {
        bool keep = (sp[26 * NG + tid] <= bxmax) & (sp[29 * NG + tid] >= bxmin) &
                    (sp[27 * NG + tid] <= bymax) & (sp[30 * NG + tid] >= bymin) &
                    (sp[28 * NG + tid] <= bzmax) & (sp[31 * NG + tid] >= bzmin);
        unsigned m = __ballot_sync(0xffffffffu, keep);
        int lane = tid & 31;
        int base = 0;
        if (lane == 0 && m) base = atomicAdd(&s_cnt, __popc(m));
        base = __shfl_sync(0xffffffffu, base, 0);
        if (keep) s_list[base + __popc(m & ((1u << lane) - 1u))] = tid;
    }
    __syncthreads();
    int ns = s_cnt;

    int n = n0 + tid;
    float px = grid[n * 3 + 0];
    float py = grid[n * 3 + 1];
    float pz = grid[n * 3 + 2];

    float cnt = 0.0f, sumd = 0.0f;
    float sumf[NF];
#pragma unroll
    for (int k = 0; k < NF; k++) sumf[k] = 0.0f;

    for (int s = 0; s < ns; s++) {
        int g = s_list[s];                       // uniform per warp -> LDS broadcast
        float dx = px - sp[0 * NG + g];
        float dy = py - sp[1 * NG + g];
        float dz = pz - sp[2 * NG + g];
        float maha = sp[3 * NG + g] * dx * dx;
        maha = fmaf(sp[4 * NG + g], dy * dy, maha);
        maha = fmaf(sp[5 * NG + g], dz * dz, maha);
        maha = fmaf(sp[6 * NG + g], dx * dy, maha);
        maha = fmaf(sp[7 * NG + g], dx * dz, maha);
        maha = fmaf(sp[8 * NG + g], dy * dz, maha);
        if (maha <= 4.0f) {
            float w = __expf(-0.5f * maha);
            cnt  += 1.0f;
            sumd = fmaf(sp[9 * NG + g], w, sumd);
#pragma unroll
            for (int k = 0; k < NF; k++)
                sumf[k] = fmaf(sp[(10 + k) * NG + g], w, sumf[k]);
        }
    }

    float inv = (cnt > 0.0f) ? (1.0f / cnt) : 0.0f;
    out[n] = sumd * inv;
    float4* fo = reinterpret_cast<float4*>(out + NVOX + (size_t)n * NF);
    fo[0] = make_float4(sumf[0] * inv,  sumf[1] * inv,  sumf[2] * inv,  sumf[3] * inv);
    fo[1] = make_float4(sumf[4] * inv,  sumf[5] * inv,  sumf[6] * inv,  sumf[7] * inv);
    fo[2] = make_float4(sumf[8] * inv,  sumf[9] * inv,  sumf[10] * inv, sumf[11] * inv);
    fo[3] = make_float4(sumf[12] * inv, sumf[13] * inv, sumf[14] * inv, sumf[15] * inv);
}

extern "C" void kernel_launch(void* const* d_in, const int* in_sizes, int n_in,
                              void* d_out, int out_size) {
    const float* grid  = (const float*)d_in[0];   // (80000, 3)
    const float* means = (const float*)d_in[1];   // (1, 128, 3)
    const float* opac  = (const float*)d_in[2];   // (1, 128, 1)
    const float* feats = (const float*)d_in[3];   // (1, 128, 16)
    const float* covs  = (const float*)d_in[4];   // (1, 128, 3, 3)
    float* out = (float*)d_out;                   // dens (80000) ++ feats (80000*16)

    gv_prep_kernel<<<1, 128>>>(means, opac, feats, covs);
    gv_splat_kernel<<<NVOX / 128, 128>>>(grid, out);
}

// round 2
// speedup vs baseline: 1.1100x; 1.1100x over previous
#include <cuda_runtime.h>
#include <math.h>

// GaussianVoxelizer: grid 100x100x8 = 80000 voxels, 128 gaussians, 16 features.
#define NVOX 80000
#define NG   128
#define NF   16
#define TPB  256
#define TILE 256
#define NBLK ((NVOX + TILE - 1) / TILE)   // 313

// Packed per-gaussian fields (stride NG):
// 0..2 mean xyz | 3..5 inv00,inv11,inv22 | 6..8 2*inv01,2*inv02,2*inv12
// 9 opacity | 10..12 bbox min | 13..15 bbox max
#define PF 16

__global__ __launch_bounds__(TPB) void gv_kernel(const float* __restrict__ grid,
                                                 const float* __restrict__ means,
                                                 const float* __restrict__ opac,
                                                 const float* __restrict__ feats,
                                                 const float* __restrict__ covs,
                                                 float* __restrict__ out) {
    __shared__ float s_feat[NG * NF];   // 8 KB raw features [g][k]
    __shared__ float s_cov[NG * 9];     // 4.5 KB raw covariances (staging)
    __shared__ float sp[PF * NG];       // 8 KB packed params
    __shared__ int   s_list[NG];
    __shared__ int   s_cnt;

    int tid = threadIdx.x;
    int n   = blockIdx.x * TILE + tid;
    bool valid = (n < NVOX);

    // Issue the grid loads early; latency overlaps the staging below.
    float px = 0.f, py = 0.f, pz = 0.f;
    if (valid) {
        px = grid[n * 3 + 0];
        py = grid[n * 3 + 1];
        pz = grid[n * 3 + 2];
    }

    // Coalesced staging of raw gaussian inputs.
#pragma unroll
    for (int i = tid; i < NG * NF; i += TPB) s_feat[i] = feats[i];
#pragma unroll
    for (int i = tid; i < NG * 9; i += TPB) s_cov[i] = covs[i];
    if (tid == 0) s_cnt = 0;
    __syncthreads();

    // Inline prep: thread g (< NG) computes inverse, bbox, packs SoA.
    if (tid < NG) {
        int g = tid;
        const float* C = s_cov + g * 9;
        float a = C[0], b = C[1], c = C[2];
        float d = C[4], e = C[5], f = C[8];
        float c00 = d * f - e * e;
        float c01 = c * e - b * f;
        float c02 = b * e - c * d;
        float det = a * c00 + b * c01 + c * c02;
        float id  = 1.0f / det;

        float mx = means[g * 3 + 0];
        float my = means[g * 3 + 1];
        float mz = means[g * 3 + 2];

        sp[0 * NG + g] = mx;
        sp[1 * NG + g] = my;
        sp[2 * NG + g] = mz;
        sp[3 * NG + g] = c00 * id;                      // i00
        sp[4 * NG + g] = (a * f - c * c) * id;          // i11
        sp[5 * NG + g] = (a * d - b * b) * id;          // i22
        sp[6 * NG + g] = 2.0f * c01 * id;               // 2*i01
        sp[7 * NG + g] = 2.0f * c02 * id;               // 2*i02
        sp[8 * NG + g] = 2.0f * (b * c - a * e) * id;   // 2*i12
        sp[9 * NG + g] = opac[g];

        // Conservative AABB of maha<=4 ellipsoid: mu +- 2*sqrt(C_kk).
        const float margin = 1e-3f;
        float ex = 2.0f * sqrtf(fmaxf(a, 0.0f)) + margin;
        float ey = 2.0f * sqrtf(fmaxf(d, 0.0f)) + margin;
        float ez = 2.0f * sqrtf(fmaxf(f, 0.0f)) + margin;
        sp[10 * NG + g] = mx - ex;
        sp[11 * NG + g] = my - ey;
        sp[12 * NG + g] = mz - ez;
        sp[13 * NG + g] = mx + ex;
        sp[14 * NG + g] = my + ey;
        sp[15 * NG + g] = mz + ez;
    }
    __syncthreads();

    // Tile AABB (voxel centers). n = (x*100 + y)*8 + z; coord = (i+0.5)*0.8 + lo.
    int n0 = blockIdx.x * TILE;
    int n1 = min(n0 + TILE - 1, NVOX - 1);
    int x0 = n0 / 800, x1 = n1 / 800;
    float bxmin = (x0 + 0.5f) * 0.8f - 40.0f;
    float bxmax = (x1 + 0.5f) * 0.8f - 40.0f;
    float bymin, bymax;
    if (x0 == x1) {
        int y0 = (n0 % 800) / 8, y1 = (n1 % 800) / 8;
        bymin = (y0 + 0.5f) * 0.8f - 40.0f;
        bymax = (y1 + 0.5f) * 0.8f - 40.0f;
    } else {
        bymin = 0.5f * 0.8f - 40.0f;
        bymax = 99.5f * 0.8f - 40.0f;
    }
    float bzmin = 0.5f * 0.8f - 1.0f;
    float bzmax = 7.5f * 0.8f - 1.0f;

    // Cull: warps 0..3 test gaussian AABB vs tile AABB, compact survivors.
    if (tid < NG) {
        bool keep = (sp[10 * NG + tid] <= bxmax) & (sp[13 * NG + tid] >= bxmin) &
                    (sp[11 * NG + tid] <= bymax) & (sp[14 * NG + tid] >= bymin) &
                    (sp[12 * NG + tid] <= bzmax) & (sp[15 * NG + tid] >= bzmin);
        unsigned m = __ballot_sync(0xffffffffu, keep);
        int lane = tid & 31;
        int base = 0;
        if (lane == 0 && m) base = atomicAdd(&s_cnt, __popc(m));
        base = __shfl_sync(0xffffffffu, base, 0);
        if (keep) s_list[base + __popc(m & ((1u << lane) - 1u))] = tid;
    }
    __syncthreads();
    int ns = s_cnt;

    float cnt = 0.0f, sumd = 0.0f;
    float sumf[NF];
#pragma unroll
    for (int k = 0; k < NF; k++) sumf[k] = 0.0f;

    for (int s = 0; s < ns; s++) {
        int g = s_list[s];                        // uniform per warp -> LDS broadcast
        float dx = px - sp[0 * NG + g];
        float dy = py - sp[1 * NG + g];
        float dz = pz - sp[2 * NG + g];
        float maha = sp[3 * NG + g] * dx * dx;
        maha = fmaf(sp[4 * NG + g], dy * dy, maha);
        maha = fmaf(sp[5 * NG + g], dz * dz, maha);
        maha = fmaf(sp[6 * NG + g], dx * dy, maha);
        maha = fmaf(sp[7 * NG + g], dx * dz, maha);
        maha = fmaf(sp[8 * NG + g], dy * dz, maha);
        if (maha <= 4.0f) {
            float w = __expf(-0.5f * maha);
            float scale = sp[9 * NG + g] * w;     // opac * w
            cnt  += 1.0f;
            sumd += scale;
            const float* fg = s_feat + g * NF;    // uniform -> broadcast
#pragma unroll
            for (int k = 0; k < NF; k++)
                sumf[k] = fmaf(scale, fg[k], sumf[k]);
        }
    }

    if (valid) {
        float inv = (cnt > 0.0f) ? (1.0f / cnt) : 0.0f;
        out[n] = sumd * inv;
        float4* fo = reinterpret_cast<float4*>(out + NVOX + (size_t)n * NF);
        fo[0] = make_float4(sumf[0] * inv,  sumf[1] * inv,  sumf[2] * inv,  sumf[3] * inv);
        fo[1] = make_float4(sumf[4] * inv,  sumf[5] * inv,  sumf[6] * inv,  sumf[7] * inv);
        fo[2] = make_float4(sumf[8] * inv,  sumf[9] * inv,  sumf[10] * inv, sumf[11] * inv);
        fo[3] = make_float4(sumf[12] * inv, sumf[13] * inv, sumf[14] * inv, sumf[15] * inv);
    }
}

extern "C" void kernel_launch(void* const* d_in, const int* in_sizes, int n_in,
                              void* d_out, int out_size) {
    const float* grid  = (const float*)d_in[0];   // (80000, 3)
    const float* means = (const float*)d_in[1];   // (1, 128, 3)
    const float* opac  = (const float*)d_in[2];   // (1, 128, 1)
    const float* feats = (const float*)d_in[3];   // (1, 128, 16)
    const float* covs  = (const float*)d_in[4];   // (1, 128, 3, 3)
    float* out = (float*)d_out;                   // dens (80000) ++ feats (80000*16)

    gv_kernel<<<NBLK, TPB>>>(grid, means, opac, feats, covs, out);
}